// round 17
// baseline (speedup 1.0000x reference)
#include <cuda_runtime.h>

#define N_NODES 100000
#define N_EDGES 1600000
#define F_IN 32
#define HID 16

// Scratch (no allocations allowed in kernel_launch).
// Device globals are zero-initialized at module load. The pipeline is
// SELF-CLEANING: node1 re-zeroes sum1 after reading; node2 re-zeroes sumh and
// deg after reading. Every launch (first run + graph replays) sees zeros.
__device__ __align__(16) float g_deg [N_NODES];
__device__ __align__(16) float g_xt  [N_NODES * HID];   // x @ W1_l.T
__device__ __align__(16) float g_xr1 [N_NODES * HID];   // x @ W1_r.T
__device__ __align__(16) float g_sum1[N_NODES * HID];   // fp32 accumulators L1
__device__ __align__(16) float g_h   [N_NODES * HID];   // relu(layer1)
__device__ __align__(16) float g_sumh[N_NODES * HID];   // fp32 accumulators L2

__device__ __forceinline__ void red_add_v4(float* addr, float4 v) {
    asm volatile("red.global.add.v4.f32 [%0], {%1,%2,%3,%4};"
                 :: "l"(addr), "f"(v.x), "f"(v.y), "f"(v.z), "f"(v.w)
                 : "memory");
}

// ---- packed f32x2 helpers (FFMA2: only reachable via PTX) ------------------
__device__ __forceinline__ unsigned long long pack_dup(float v) {
    unsigned long long r;
    asm("mov.b64 %0, {%1, %1};" : "=l"(r) : "f"(v));
    return r;
}
__device__ __forceinline__ unsigned long long pack_pair(float lo, float hi) {
    unsigned long long r;
    asm("mov.b64 %0, {%1, %2};" : "=l"(r) : "f"(lo), "f"(hi));
    return r;
}
__device__ __forceinline__ void ffma2(unsigned long long& d,
                                      unsigned long long a,
                                      unsigned long long b) {
    asm("fma.rn.f32x2 %0, %1, %2, %0;" : "+l"(d) : "l"(a), "l"(b));
}

// ---------------------------------------------------------------------------
// 1) k_pre: 1 thread/node. xt = x@W1l.T and xr1 = x@W1r.T from one read of x.
//    Weights pre-packed in smem as output-pair float2 at each k; inner loop is
//    LDS.128 (2 pairs) + FFMA2. No zero-fill (buffers self-clean).
// ---------------------------------------------------------------------------
__global__ void __launch_bounds__(256) k_pre(const float* __restrict__ x,
                                             const float* __restrict__ W1l,
                                             const float* __restrict__ W1r) {
    // WlP[k*8 + p] = (W1l[2p][k], W1l[2p+1][k])
    __shared__ __align__(16) float2 WlP[F_IN * (HID / 2)];
    __shared__ __align__(16) float2 WrP[F_IN * (HID / 2)];
    for (int i = threadIdx.x; i < F_IN * (HID / 2); i += blockDim.x) {
        int k = i >> 3;
        int p = i & 7;
        WlP[i] = make_float2(W1l[(2 * p) * F_IN + k], W1l[(2 * p + 1) * F_IN + k]);
        WrP[i] = make_float2(W1r[(2 * p) * F_IN + k], W1r[(2 * p + 1) * F_IN + k]);
    }
    __syncthreads();

    int n = blockIdx.x * blockDim.x + threadIdx.x;
    if (n >= N_NODES) return;

    float xr[F_IN];
    const float4* xp = reinterpret_cast<const float4*>(x + (size_t)n * F_IN);
#pragma unroll
    for (int g = 0; g < F_IN / 4; g++) {
        float4 v = __ldg(xp + g);
        xr[4*g+0] = v.x; xr[4*g+1] = v.y; xr[4*g+2] = v.z; xr[4*g+3] = v.w;
    }

    const ulonglong2* wlp = reinterpret_cast<const ulonglong2*>(WlP);
    const ulonglong2* wrp = reinterpret_cast<const ulonglong2*>(WrP);

    unsigned long long accT[HID / 2], accR[HID / 2];
#pragma unroll
    for (int p = 0; p < HID / 2; p++) { accT[p] = 0ull; accR[p] = 0ull; }

#pragma unroll
    for (int k = 0; k < F_IN; k++) {
        unsigned long long xk = pack_dup(xr[k]);
#pragma unroll
        for (int j = 0; j < 4; j++) {          // 4 x ulonglong2 = 8 pairs
            ulonglong2 wl = wlp[k * 4 + j];
            ffma2(accT[2*j],   xk, wl.x);
            ffma2(accT[2*j+1], xk, wl.y);
            ulonglong2 wr = wrp[k * 4 + j];
            ffma2(accR[2*j],   xk, wr.x);
            ffma2(accR[2*j+1], xk, wr.y);
        }
    }

    ulonglong2* op_t = reinterpret_cast<ulonglong2*>(g_xt  + (size_t)n * HID);
    ulonglong2* op_r = reinterpret_cast<ulonglong2*>(g_xr1 + (size_t)n * HID);
#pragma unroll
    for (int j = 0; j < HID / 4; j++) {
        op_t[j] = make_ulonglong2(accT[2*j], accT[2*j+1]);
        op_r[j] = make_ulonglong2(accR[2*j], accR[2*j+1]);
    }
}

// ---------------------------------------------------------------------------
// 2) scatter1: sum1[dst] += xt[src]; deg[dst] += 1  (4 thr/edge, PDL)
// ---------------------------------------------------------------------------
__global__ void k_scatter1(const int* __restrict__ ei) {
    unsigned t = blockIdx.x * blockDim.x + threadIdx.x;
    unsigned e = t >> 2;
    unsigned q = t & 3;
    int s = 0, d = 0;
    if (e < N_EDGES) {
        s = __ldcs(ei + e);
        d = __ldcs(ei + N_EDGES + e);
    }
    cudaGridDependencySynchronize();
    if (e >= N_EDGES) return;

    if (q == 0) atomicAdd(&g_deg[d], 1.0f);

    float4 v = *reinterpret_cast<const float4*>(g_xt + (size_t)s * HID + q * 4);
    red_add_v4(g_sum1 + (size_t)d * HID + q * 4, v);
}

// ---------------------------------------------------------------------------
// 3) node1: h = relu(sum1/max(deg,1) + b1 + xr1)  (4 thr/node, PDL)
//    Re-zeroes sum1 after reading. deg NOT zeroed (node2 reads it).
// ---------------------------------------------------------------------------
__global__ void k_node1(const float* __restrict__ b1) {
    unsigned t = blockIdx.x * blockDim.x + threadIdx.x;
    unsigned n = t >> 2;
    unsigned q = t & 3;
    float4 b = make_float4(0.f, 0.f, 0.f, 0.f);
    if (n < N_NODES) b = __ldg(reinterpret_cast<const float4*>(b1) + q);
    cudaGridDependencySynchronize();
    if (n >= N_NODES) return;

    float inv = 1.0f / fmaxf(__ldg(&g_deg[n]), 1.0f);
    float4 s = *reinterpret_cast<const float4*>(g_sum1 + (size_t)n * HID + q * 4);
    float4 r = *reinterpret_cast<const float4*>(g_xr1  + (size_t)n * HID + q * 4);

    float4 o;
    o.x = fmaxf(s.x * inv + b.x + r.x, 0.0f);
    o.y = fmaxf(s.y * inv + b.y + r.y, 0.0f);
    o.z = fmaxf(s.z * inv + b.z + r.z, 0.0f);
    o.w = fmaxf(s.w * inv + b.w + r.w, 0.0f);
    *reinterpret_cast<float4*>(g_h + (size_t)n * HID + q * 4) = o;

    // self-clean for next replay
    *reinterpret_cast<float4*>(g_sum1 + (size_t)n * HID + q * 4) =
        make_float4(0.f, 0.f, 0.f, 0.f);
}

// ---------------------------------------------------------------------------
// 4) scatter2: sumh[dst] += h[src]  (4 thr/edge, PDL)
// ---------------------------------------------------------------------------
__global__ void k_scatter2(const int* __restrict__ ei) {
    unsigned t = blockIdx.x * blockDim.x + threadIdx.x;
    unsigned e = t >> 2;
    unsigned q = t & 3;
    int s = 0, d = 0;
    if (e < N_EDGES) {
        s = __ldcs(ei + e);
        d = __ldcs(ei + N_EDGES + e);
    }
    cudaGridDependencySynchronize();
    if (e >= N_EDGES) return;

    float4 v = *reinterpret_cast<const float4*>(g_h + (size_t)s * HID + q * 4);
    red_add_v4(g_sumh + (size_t)d * HID + q * 4, v);
}

// ---------------------------------------------------------------------------
// 5) node2: out = (sumh*inv)@W2_l.T + b2 + h@W2_r.T  (1 thr/node, PDL)
//    Packed FFMA2 over output pairs; re-zeroes sumh and deg after reading.
// ---------------------------------------------------------------------------
__global__ void __launch_bounds__(256) k_node2(float* __restrict__ out,
                        const float* __restrict__ W2l,
                        const float* __restrict__ b2,
                        const float* __restrict__ W2r) {
    // WlP[k*16 + p] = (W2l[2p][k], W2l[2p+1][k]),  k in [0,16), p in [0,16)
    __shared__ __align__(16) float2 WlP[HID * (F_IN / 2)];
    __shared__ __align__(16) float2 WrP[HID * (F_IN / 2)];
    __shared__ float bs[F_IN];
    for (int i = threadIdx.x; i < HID * (F_IN / 2); i += blockDim.x) {
        int k = i >> 4;
        int p = i & 15;
        WlP[i] = make_float2(W2l[(2 * p) * HID + k], W2l[(2 * p + 1) * HID + k]);
        WrP[i] = make_float2(W2r[(2 * p) * HID + k], W2r[(2 * p + 1) * HID + k]);
    }
    if (threadIdx.x < F_IN) bs[threadIdx.x] = b2[threadIdx.x];
    __syncthreads();

    cudaGridDependencySynchronize();

    int n = blockIdx.x * blockDim.x + threadIdx.x;
    if (n >= N_NODES) return;

    float inv = 1.0f / fmaxf(g_deg[n], 1.0f);

    float hr[HID], ar[HID];
    const float4* hp = reinterpret_cast<const float4*>(g_h    + (size_t)n * HID);
    float4*       ap = reinterpret_cast<float4*>(g_sumh + (size_t)n * HID);
#pragma unroll
    for (int g = 0; g < HID / 4; g++) {
        float4 v = hp[g];
        hr[4*g+0] = v.x; hr[4*g+1] = v.y; hr[4*g+2] = v.z; hr[4*g+3] = v.w;
        float4 a = ap[g];
        ar[4*g+0] = a.x * inv; ar[4*g+1] = a.y * inv;
        ar[4*g+2] = a.z * inv; ar[4*g+3] = a.w * inv;
    }

    // self-clean for next replay
    float4 z = make_float4(0.f, 0.f, 0.f, 0.f);
#pragma unroll
    for (int g = 0; g < HID / 4; g++) ap[g] = z;
    g_deg[n] = 0.0f;

    const ulonglong2* wlp = reinterpret_cast<const ulonglong2*>(WlP);
    const ulonglong2* wrp = reinterpret_cast<const ulonglong2*>(WrP);

    unsigned long long acc[F_IN / 2];
#pragma unroll
    for (int p = 0; p < F_IN / 2; p++) acc[p] = pack_pair(bs[2*p], bs[2*p+1]);

#pragma unroll
    for (int k = 0; k < HID; k++) {
        unsigned long long ak = pack_dup(ar[k]);
        unsigned long long hk = pack_dup(hr[k]);
#pragma unroll
        for (int j = 0; j < 8; j++) {          // 8 x ulonglong2 = 16 pairs
            ulonglong2 wl = wlp[k * 8 + j];
            ffma2(acc[2*j],   ak, wl.x);
            ffma2(acc[2*j+1], ak, wl.y);
            ulonglong2 wr = wrp[k * 8 + j];
            ffma2(acc[2*j],   hk, wr.x);
            ffma2(acc[2*j+1], hk, wr.y);
        }
    }

    ulonglong2* op = reinterpret_cast<ulonglong2*>(out + (size_t)n * F_IN);
#pragma unroll
    for (int j = 0; j < F_IN / 4; j++) {
        op[j] = make_ulonglong2(acc[2*j], acc[2*j+1]);
    }
}

// ---------------------------------------------------------------------------
// PDL launch helper (implicit completion at grid exit — no early triggers)
// ---------------------------------------------------------------------------
static void launch_pdl(const void* func, int grid, int block, void** args) {
    cudaLaunchConfig_t cfg = {};
    cfg.gridDim  = dim3(grid, 1, 1);
    cfg.blockDim = dim3(block, 1, 1);
    cfg.stream = 0;
    cudaLaunchAttribute attr[1];
    attr[0].id = cudaLaunchAttributeProgrammaticStreamSerialization;
    attr[0].val.programmaticStreamSerializationAllowed = 1;
    cfg.attrs = attr;
    cfg.numAttrs = 1;
    cudaLaunchKernelExC(&cfg, func, args);
}

extern "C" void kernel_launch(void* const* d_in, const int* in_sizes, int n_in,
                              void* d_out, int out_size) {
    const float* x   = (const float*)d_in[0];
    const int*   ei  = (const int*)d_in[1];   // [1,2,E], int32 (JAX x64 off)
    const float* W1l = (const float*)d_in[2];
    const float* b1  = (const float*)d_in[3];
    const float* W1r = (const float*)d_in[4];
    const float* W2l = (const float*)d_in[5];
    const float* b2  = (const float*)d_in[6];
    const float* W2r = (const float*)d_in[7];
    float*       out = (float*)d_out;

    const int T = 256;
    const int grid_node  = (N_NODES + T - 1) / T;
    const int grid_node4 = (N_NODES * 4 + T - 1) / T;
    const int grid_edge4 = ((N_EDGES * 4) + T - 1) / T;

    k_pre<<<grid_node, T>>>(x, W1l, W1r);

    {
        void* args[] = { (void*)&ei };
        launch_pdl((const void*)k_scatter1, grid_edge4, T, args);
    }
    {
        void* args[] = { (void*)&b1 };
        launch_pdl((const void*)k_node1, grid_node4, T, args);
    }
    {
        void* args[] = { (void*)&ei };
        launch_pdl((const void*)k_scatter2, grid_edge4, T, args);
    }
    {
        void* args[] = { (void*)&out, (void*)&W2l, (void*)&b2, (void*)&W2r };
        launch_pdl((const void*)k_node2, grid_node, T, args);
    }
}